// round 2
// baseline (speedup 1.0000x reference)
#include <cuda_runtime.h>
#include <math.h>

#define B 64
#define C 256
#define H 56
#define W 56
#define HW (H*W)
#define CHW (C*HW)

#define TW 8
#define TH 32
#define HALO_H (TH+8)   // 40
#define HALO_W (TW+8)   // 16
#define HPITCH 20       // padded halo row (floats) to reduce bank conflicts
#define CCH 16          // channels per smem chunk
#define THREADS 288     // 32 rows * 9 dy

__device__ float g_inv_norm[B*HW];

// ---------------------------------------------------------------------------
// Pass 1: inv_norm[b,y,x] = 1 / max(sqrt(sum_c x^2), 1e-12)
// ---------------------------------------------------------------------------
__global__ void norm_kernel(const float* __restrict__ x) {
    int p4 = blockIdx.x * blockDim.x + threadIdx.x;   // one float4 of pixels
    if (p4 >= B*HW/4) return;
    int b  = p4 / (HW/4);
    int s4 = p4 % (HW/4);
    const float4* px = (const float4*)(x + (size_t)b*CHW) + s4;
    float a0=0.f, a1=0.f, a2=0.f, a3=0.f;
    #pragma unroll 4
    for (int c = 0; c < C; c++) {
        float4 v = px[(size_t)c*(HW/4)];
        a0 = fmaf(v.x, v.x, a0);
        a1 = fmaf(v.y, v.y, a1);
        a2 = fmaf(v.z, v.z, a2);
        a3 = fmaf(v.w, v.w, a3);
    }
    float4 r;
    r.x = 1.f / fmaxf(sqrtf(a0), 1e-12f);
    r.y = 1.f / fmaxf(sqrtf(a1), 1e-12f);
    r.z = 1.f / fmaxf(sqrtf(a2), 1e-12f);
    r.w = 1.f / fmaxf(sqrtf(a3), 1e-12f);
    ((float4*)g_inv_norm)[p4] = r;
}

// ---------------------------------------------------------------------------
// Pass 2: correlation volume + argmax + gaussian soft-argmax
// Grid: (7 xtiles, 2 ytiles, 64 images). Block: 288 threads.
// Thread t: dy = t%9, row = t/9 (0..31). Owns 8 centers x 9 dx = 72 accums.
// ---------------------------------------------------------------------------
__global__ __launch_bounds__(THREADS, 2)
void corr_kernel(const float* __restrict__ x, float* __restrict__ out) {
    const int tx0 = blockIdx.x * TW;
    const int ty0 = blockIdx.y * TH;
    const int b   = blockIdx.z;

    extern __shared__ float smem[];
    float* sc = smem;                 // [CCH][TH][TW]    = 4096 floats
    float* sh = smem + CCH*TH*TW;     // [CCH][40][20]    = 12800 floats (also rbuf)

    const int t = threadIdx.x;
    float* outp = out + (size_t)b * 3 * HW;

    // First frame of each 8-segment: x_post == 0 -> mot = 0, conf = 0.
    if ((b & 7) == 0) {
        for (int i = t; i < TH*TW; i += THREADS) {
            int ly = i / TW, lx = i % TW;
            int gy = ty0 + ly;
            if (gy < H) {
                int o = gy*W + tx0 + lx;
                outp[o]        = 0.f;
                outp[HW + o]   = 0.f;
                outp[2*HW + o] = 0.f;
            }
        }
        return;
    }

    const float* xc  = x + (size_t)b     * CHW;
    const float* xp  = x + (size_t)(b-1) * CHW;
    const float* inC = g_inv_norm + b     * HW;
    const float* inP = g_inv_norm + (b-1) * HW;

    const int dy  = t % 9;
    const int row = t / 9;           // 0..31

    float acc[72];
    #pragma unroll
    for (int i = 0; i < 72; i++) acc[i] = 0.f;

    for (int ch0 = 0; ch0 < C; ch0 += CCH) {
        __syncthreads();   // previous chunk's smem reads done

        // ---- load center tile (normalized) ----
        for (int i = t; i < CCH*TH*TW; i += THREADS) {
            int c  = i >> 8;            // TH*TW == 256
            int r2 = (i >> 3) & 31;
            int xx = i & 7;
            int gy = ty0 + r2;
            float v = 0.f;
            if (gy < H) {
                int o = gy*W + tx0 + xx;
                v = xc[(size_t)(ch0 + c)*HW + o] * inC[o];
            }
            sc[i] = v;
        }
        // ---- load halo tile from previous frame (normalized, zero-padded) ----
        for (int i = t; i < CCH*HALO_H*HALO_W; i += THREADS) {
            int c   = i / (HALO_H*HALO_W);
            int rem = i % (HALO_H*HALO_W);
            int hy  = rem / HALO_W;
            int hx  = rem % HALO_W;
            int gy  = ty0 + hy - 4;
            int gx  = tx0 + hx - 4;
            float v = 0.f;
            if (gy >= 0 && gy < H && gx >= 0 && gx < W) {
                int o = gy*W + gx;
                v = xp[(size_t)(ch0 + c)*HW + o] * inP[o];
            }
            sh[c*(HALO_H*HPITCH) + hy*HPITCH + hx] = v;
        }
        __syncthreads();

        // ---- correlate ----
        #pragma unroll 2
        for (int c = 0; c < CCH; c++) {
            const float* cp = &sc[c*(TH*TW) + row*TW];
            float4 v0 = *(const float4*)(cp);
            float4 v1 = *(const float4*)(cp + 4);
            const float* hr = &sh[c*(HALO_H*HPITCH) + (row + dy)*HPITCH];
            float4 h0 = *(const float4*)(hr);
            float4 h1 = *(const float4*)(hr + 4);
            float4 h2 = *(const float4*)(hr + 8);
            float4 h3 = *(const float4*)(hr + 12);

            float v[8]  = {v0.x, v0.y, v0.z, v0.w, v1.x, v1.y, v1.z, v1.w};
            float hh[16] = {h0.x, h0.y, h0.z, h0.w, h1.x, h1.y, h1.z, h1.w,
                            h2.x, h2.y, h2.z, h2.w, h3.x, h3.y, h3.z, h3.w};
            #pragma unroll
            for (int i = 0; i < 8; i++) {
                #pragma unroll
                for (int dx = 0; dx < 9; dx++)
                    acc[i*9 + dx] = fmaf(v[i], hh[i + dx], acc[i*9 + dx]);
            }
        }
    }

    // ---- postprocess in two row-halves (rbuf aliases halo smem) ----
    for (int half = 0; half < 2; half++) {
        __syncthreads();
        if (row >= half*16 && row < half*16 + 16) {
            int lr = row - half*16;
            #pragma unroll
            for (int i = 0; i < 8; i++) {
                int pix = lr*TW + i;
                #pragma unroll
                for (int dx = 0; dx < 9; dx++)
                    sh[pix*81 + dy*9 + dx] = acc[i*9 + dx];
            }
        }
        __syncthreads();
        if (t < 128) {
            int pix = t;
            int ly = half*16 + (pix >> 3);
            int lx = pix & 7;
            int gy = ty0 + ly;
            if (gy < H) {
                const float* r = &sh[pix*81];
                // argmax, first index wins on ties (matches jnp.argmax)
                float best = -INFINITY;
                int bi = 0;
                #pragma unroll
                for (int k = 0; k < 81; k++) {
                    float v = r[k];
                    if (v > best) { best = v; bi = k; }
                }
                int biy = bi / 9, bix = bi - biy*9;
                float s = 0.f, sumh = 0.f, sumv = 0.f;
                #pragma unroll
                for (int ky = 0; ky < 9; ky++) {
                    float ddy = (float)(ky - biy);
                    float dy2 = ddy*ddy;
                    #pragma unroll
                    for (int kx = 0; kx < 9; kx++) {
                        float ddx = (float)(kx - bix);
                        float g = expf(-50.0f * (dy2 + ddx*ddx)); // 1/(2*0.1^2)=50
                        float f = g * r[ky*9 + kx] * 10.0f;       // BETA
                        s    += f;
                        sumh += f * (float)(ky - 4);
                        sumv += f * (float)(kx - 4);
                    }
                }
                s += 1e-12f;
                int o = gy*W + tx0 + lx;
                outp[o]        = sumh / s;
                outp[HW + o]   = sumv / s;
                outp[2*HW + o] = best;
            }
        }
    }
}

// ---------------------------------------------------------------------------
extern "C" void kernel_launch(void* const* d_in, const int* in_sizes, int n_in,
                              void* d_out, int out_size) {
    const float* x = (const float*)d_in[0];
    float* out = (float*)d_out;

    norm_kernel<<<(B*HW/4 + 255)/256, 256>>>(x);

    const int smem_bytes = (CCH*TH*TW + CCH*HALO_H*HPITCH) * (int)sizeof(float); // 67584
    cudaFuncSetAttribute(corr_kernel, cudaFuncAttributeMaxDynamicSharedMemorySize, smem_bytes);

    dim3 grid(W/TW, (H + TH - 1)/TH, B);   // (7, 2, 64)
    corr_kernel<<<grid, THREADS, smem_bytes>>>(x, out);
}

// round 3
// speedup vs baseline: 1.7621x; 1.7621x over previous
#include <cuda_runtime.h>
#include <math.h>

#define B 64
#define C 256
#define H 56
#define W 56
#define HW (H*W)
#define CHW (C*HW)

#define TW 8            // tile width (centers)
#define TH 14           // tile height (56/14 = 4 exact)
#define HALO_H (TH+8)   // 22
#define HALO_W 16       // 12 used + pad to quad
#define HPITCH 20       // padded halo row (floats)
#define CCH 16          // channels per smem chunk
#define THREADS 252     // 14 rows * 2 xh * 9 dy

#define SC_CH (TH*TW)        // 112 floats per channel (center)
#define SH_CH (HALO_H*HPITCH)// 440 floats per channel (halo)
#define NPIX (TH*TW)         // 112 pixels per tile
#define SMEM_FLOATS (NPIX*81 > CCH*(SC_CH+SH_CH) ? NPIX*81 : CCH*(SC_CH+SH_CH)) // 9072

__device__ float g_inv_norm[B*HW];

// ---------------------------------------------------------------------------
// Pass 1: inv_norm[b,y,x] = 1 / max(sqrt(sum_c x^2), 1e-12)
// ---------------------------------------------------------------------------
__global__ void norm_kernel(const float* __restrict__ x) {
    int p4 = blockIdx.x * blockDim.x + threadIdx.x;   // one float4 of pixels
    if (p4 >= B*HW/4) return;
    int b  = p4 / (HW/4);
    int s4 = p4 % (HW/4);
    const float4* px = (const float4*)(x + (size_t)b*CHW) + s4;
    float a0=0.f, a1=0.f, a2=0.f, a3=0.f;
    #pragma unroll 8
    for (int c = 0; c < C; c++) {
        float4 v = px[(size_t)c*(HW/4)];
        a0 = fmaf(v.x, v.x, a0);
        a1 = fmaf(v.y, v.y, a1);
        a2 = fmaf(v.z, v.z, a2);
        a3 = fmaf(v.w, v.w, a3);
    }
    float4 r;
    r.x = 1.f / fmaxf(sqrtf(a0), 1e-12f);
    r.y = 1.f / fmaxf(sqrtf(a1), 1e-12f);
    r.z = 1.f / fmaxf(sqrtf(a2), 1e-12f);
    r.w = 1.f / fmaxf(sqrtf(a3), 1e-12f);
    ((float4*)g_inv_norm)[p4] = r;
}

// ---------------------------------------------------------------------------
// Pass 2: correlation volume + argmax + gaussian soft-argmax
// Grid: (7 xtiles, 4 ytiles, 64 images). Block: 252 threads.
// Thread t: dy = t%9; q = t/9; xh = q%2; row = q/2 (0..13).
// Owns 4 centers (cols xh*4..xh*4+3) x 9 dx = 36 accumulators.
// ---------------------------------------------------------------------------
__global__ __launch_bounds__(THREADS, 3)
void corr_kernel(const float* __restrict__ x, float* __restrict__ out) {
    const int tx0 = blockIdx.x * TW;
    const int ty0 = blockIdx.y * TH;
    const int b   = blockIdx.z;

    extern __shared__ float smem[];
    float* sc = smem;               // [CCH][14][8]
    float* sh = smem + CCH*SC_CH;   // [CCH][22][20]
    // rbuf aliases the whole smem after compute: [112][81]

    const int t = threadIdx.x;
    float* outp = out + (size_t)b * 3 * HW;

    // First frame of each 8-segment: x_post == 0 -> mot = 0, conf = 0.
    if ((b & 7) == 0) {
        for (int i = t; i < NPIX; i += THREADS) {
            int o = (ty0 + i/TW)*W + tx0 + (i%TW);
            outp[o]        = 0.f;
            outp[HW + o]   = 0.f;
            outp[2*HW + o] = 0.f;
        }
        return;
    }

    const float* xc  = x + (size_t)b     * CHW;
    const float* xp  = x + (size_t)(b-1) * CHW;
    const float* inC = g_inv_norm + b     * HW;
    const float* inP = g_inv_norm + (b-1) * HW;

    const int dy  = t % 9;
    const int q   = t / 9;
    const int xh  = q & 1;          // 0 or 1
    const int row = q >> 1;         // 0..13

    float acc[36];
    #pragma unroll
    for (int i = 0; i < 36; i++) acc[i] = 0.f;

    const int sc_off = row*TW + xh*4;
    const int sh_off = (row + dy)*HPITCH + xh*4;

    for (int ch0 = 0; ch0 < C; ch0 += CCH) {
        __syncthreads();   // previous chunk's smem reads done

        // ---- fill center tile (normalized), float4 granularity ----
        // quads: CCH * 14 rows * 2 quads = 448
        for (int i = t; i < CCH*TH*2; i += THREADS) {
            int c   = i / (TH*2);
            int rem = i - c*(TH*2);
            int r2  = rem >> 1;
            int lq  = (rem & 1) * 4;
            int o   = (ty0 + r2)*W + tx0 + lq;
            float4 v = *(const float4*)(xc + (size_t)(ch0 + c)*HW + o);
            float4 n = *(const float4*)(inC + o);
            v.x *= n.x; v.y *= n.y; v.z *= n.z; v.w *= n.w;
            *(float4*)&sc[c*SC_CH + r2*TW + lq] = v;
        }
        // ---- fill halo tile from previous frame, float4 granularity ----
        // quads: CCH * 22 rows * 4 quads = 1408
        for (int i = t; i < CCH*HALO_H*4; i += THREADS) {
            int c   = i / (HALO_H*4);
            int rem = i - c*(HALO_H*4);
            int hy  = rem >> 2;
            int hx  = (rem & 3) * 4;
            int gy  = ty0 + hy - 4;
            int gx  = tx0 + hx - 4;
            float4 v = {0.f, 0.f, 0.f, 0.f};
            if (gy >= 0 && gy < H && gx >= 0 && gx < W) {   // quads fully in or out
                int o = gy*W + gx;
                float4 d = *(const float4*)(xp + (size_t)(ch0 + c)*HW + o);
                float4 n = *(const float4*)(inP + o);
                v.x = d.x*n.x; v.y = d.y*n.y; v.z = d.z*n.z; v.w = d.w*n.w;
            }
            *(float4*)&sh[c*SH_CH + hy*HPITCH + hx] = v;
        }
        __syncthreads();

        // ---- correlate ----
        const float* scp = sc + sc_off;
        const float* shp = sh + sh_off;
        #pragma unroll 2
        for (int c = 0; c < CCH; c++) {
            float4 v4 = *(const float4*)scp;
            float4 h0 = *(const float4*)shp;
            float4 h1 = *(const float4*)(shp + 4);
            float4 h2 = *(const float4*)(shp + 8);
            scp += SC_CH;
            shp += SH_CH;
            float v[4]  = {v4.x, v4.y, v4.z, v4.w};
            float h[12] = {h0.x, h0.y, h0.z, h0.w,
                           h1.x, h1.y, h1.z, h1.w,
                           h2.x, h2.y, h2.z, h2.w};
            #pragma unroll
            for (int i = 0; i < 4; i++)
                #pragma unroll
                for (int dx = 0; dx < 9; dx++)
                    acc[i*9 + dx] = fmaf(v[i], h[i + dx], acc[i*9 + dx]);
        }
    }

    // ---- dump accumulators to smem rbuf [112 pixels][81] ----
    __syncthreads();
    {
        float* rb = smem;
        #pragma unroll
        for (int i = 0; i < 4; i++) {
            int pix = row*TW + xh*4 + i;
            #pragma unroll
            for (int dx = 0; dx < 9; dx++)
                rb[pix*81 + dy*9 + dx] = acc[i*9 + dx];
        }
    }
    __syncthreads();

    // ---- postprocess: one thread per pixel ----
    if (t < NPIX) {
        const float* r = smem + t*81;
        int ly = t / TW, lx = t % TW;
        // argmax, first index wins on ties (matches jnp.argmax)
        float best = -INFINITY;
        int bi = 0;
        #pragma unroll
        for (int k = 0; k < 81; k++) {
            float v = r[k];
            if (v > best) { best = v; bi = k; }
        }
        int biy = bi / 9, bix = bi - biy*9;
        float s = 0.f, sumh = 0.f, sumv = 0.f;
        #pragma unroll
        for (int ky = 0; ky < 9; ky++) {
            float ddy = (float)(ky - biy);
            float dy2 = ddy*ddy;
            #pragma unroll
            for (int kx = 0; kx < 9; kx++) {
                float ddx = (float)(kx - bix);
                float g = expf(-50.0f * (dy2 + ddx*ddx)); // 1/(2*0.1^2)=50
                float f = g * r[ky*9 + kx] * 10.0f;       // BETA
                s    += f;
                sumh += f * (float)(ky - 4);
                sumv += f * (float)(kx - 4);
            }
        }
        s += 1e-12f;
        int o = (ty0 + ly)*W + tx0 + lx;
        outp[o]        = sumh / s;
        outp[HW + o]   = sumv / s;
        outp[2*HW + o] = best;
    }
}

// ---------------------------------------------------------------------------
extern "C" void kernel_launch(void* const* d_in, const int* in_sizes, int n_in,
                              void* d_out, int out_size) {
    const float* x = (const float*)d_in[0];
    float* out = (float*)d_out;

    norm_kernel<<<(B*HW/4 + 255)/256, 256>>>(x);

    const int smem_bytes = SMEM_FLOATS * (int)sizeof(float);   // 36288
    cudaFuncSetAttribute(corr_kernel, cudaFuncAttributeMaxDynamicSharedMemorySize, smem_bytes);

    dim3 grid(W/TW, H/TH, B);   // (7, 4, 64)
    corr_kernel<<<grid, THREADS, smem_bytes>>>(x, out);
}

// round 4
// speedup vs baseline: 2.2775x; 1.2925x over previous
#include <cuda_runtime.h>
#include <math.h>

#define B 64
#define C 256
#define H 56
#define W 56
#define HW (H*W)
#define CHW (C*HW)

#define TW 8            // tile width (centers)
#define TH 14           // tile height (56/14 = 4 exact)
#define HALO_H (TH+8)   // 22
#define HPITCH 20       // padded halo row (floats)
#define CCH 16          // channels per smem chunk
#define NCHUNK (C/CCH)  // 16
#define THREADS 252     // 14 rows * 2 xh * 9 dy

#define SC_CH (TH*TW)         // 112 floats per channel (center)
#define SH_CH (HALO_H*HPITCH) // 440 floats per channel (halo)
#define BUF_FLOATS (CCH*(SC_CH+SH_CH))  // 8832
#define NPIX (TH*TW)          // 112
#define INPH_OFF (2*BUF_FLOATS)         // 17664
#define SMEM_FLOATS (INPH_OFF + SH_CH)  // 18104

__device__ float g_inv_norm[B*HW];

__device__ __forceinline__ void cpa16(unsigned dst, const float* src, int srcsz) {
    asm volatile("cp.async.cg.shared.global [%0], [%1], 16, %2;\n"
                 :: "r"(dst), "l"(src), "r"(srcsz));
}
__device__ __forceinline__ void cpa_commit() {
    asm volatile("cp.async.commit_group;\n");
}

// ---------------------------------------------------------------------------
// Pass 1: inv_norm[b,y,x] = 1 / max(sqrt(sum_c x^2), 1e-12)
// ---------------------------------------------------------------------------
__global__ void norm_kernel(const float* __restrict__ x) {
    int p4 = blockIdx.x * blockDim.x + threadIdx.x;
    if (p4 >= B*HW/4) return;
    int b  = p4 / (HW/4);
    int s4 = p4 % (HW/4);
    const float4* px = (const float4*)(x + (size_t)b*CHW) + s4;
    float a0=0.f, a1=0.f, a2=0.f, a3=0.f;
    #pragma unroll 8
    for (int c = 0; c < C; c++) {
        float4 v = px[(size_t)c*(HW/4)];
        a0 = fmaf(v.x, v.x, a0);
        a1 = fmaf(v.y, v.y, a1);
        a2 = fmaf(v.z, v.z, a2);
        a3 = fmaf(v.w, v.w, a3);
    }
    float4 r;
    r.x = 1.f / fmaxf(sqrtf(a0), 1e-12f);
    r.y = 1.f / fmaxf(sqrtf(a1), 1e-12f);
    r.z = 1.f / fmaxf(sqrtf(a2), 1e-12f);
    r.w = 1.f / fmaxf(sqrtf(a3), 1e-12f);
    ((float4*)g_inv_norm)[p4] = r;
}

// ---------------------------------------------------------------------------
// Pass 2: raw correlation (normalization factored out) + argmax + soft-argmax
// Grid: (7, 4, 64). Block: 252 threads. Thread: dy=t%9, xh=(t/9)&1, row=t/18.
// cp.async ping-pong pipeline over 16 channel chunks.
// ---------------------------------------------------------------------------
__global__ __launch_bounds__(THREADS, 3)
void corr_kernel(const float* __restrict__ x, float* __restrict__ out) {
    const int tx0 = blockIdx.x * TW;
    const int ty0 = blockIdx.y * TH;
    const int b   = blockIdx.z;

    extern __shared__ float smem[];
    const int t = threadIdx.x;
    float* outp = out + (size_t)b * 3 * HW;

    if ((b & 7) == 0) {   // first frame of each segment: x_post == 0
        for (int i = t; i < NPIX; i += THREADS) {
            int o = (ty0 + i/TW)*W + tx0 + (i%TW);
            outp[o]        = 0.f;
            outp[HW + o]   = 0.f;
            outp[2*HW + o] = 0.f;
        }
        return;
    }

    const float* xc  = x + (size_t)b     * CHW;
    const float* xp  = x + (size_t)(b-1) * CHW;
    const float* inC = g_inv_norm + b     * HW;
    const float* inP = g_inv_norm + (b-1) * HW;

    unsigned smem_u32;
    { unsigned long long tmp;
      asm("cvta.to.shared.u64 %0, %1;" : "=l"(tmp) : "l"(smem));
      smem_u32 = (unsigned)tmp; }

    // ---- async fill of one chunk (pure copy, no norm) ----
    auto prefetch = [&](int chunk, int buf) {
        const int ch0 = chunk * CCH;
        unsigned bb = smem_u32 + buf * (BUF_FLOATS*4);
        // center: 448 quads
        for (int i = t; i < CCH*TH*2; i += THREADS) {
            int c   = i / (TH*2);
            int rem = i - c*(TH*2);
            int r2  = rem >> 1;
            int lq  = (rem & 1) * 4;
            cpa16(bb + (c*SC_CH + r2*TW + lq)*4,
                  xc + (size_t)(ch0 + c)*HW + (ty0 + r2)*W + tx0 + lq, 16);
        }
        // halo: 1408 quads (quads fully in or out of bounds)
        unsigned hb = bb + CCH*SC_CH*4;
        for (int i = t; i < CCH*HALO_H*4; i += THREADS) {
            int c   = i / (HALO_H*4);
            int rem = i - c*(HALO_H*4);
            int hy  = rem >> 2;
            int hx  = (rem & 3) * 4;
            int gy  = ty0 + hy - 4;
            int gx  = tx0 + hx - 4;
            bool in = (gy >= 0 && gy < H && gx >= 0 && gx < W);
            const float* src = in ? (xp + (size_t)(ch0 + c)*HW + gy*W + gx) : xp;
            cpa16(hb + (c*SH_CH + hy*HPITCH + hx)*4, src, in ? 16 : 0);
        }
        cpa_commit();
    };

    prefetch(0, 0);

    // ---- stage inP halo tile once (needed only in postprocess) ----
    float* inPh = smem + INPH_OFF;
    for (int i = t; i < SH_CH; i += THREADS) {
        int hy = i / HPITCH, hx = i - hy*HPITCH;
        int gy = ty0 + hy - 4, gx = tx0 + hx - 4;
        inPh[i] = (gy >= 0 && gy < H && gx >= 0 && gx < W && hx < 16)
                  ? inP[gy*W + gx] : 0.f;
    }

    const int dy  = t % 9;
    const int q_  = t / 9;
    const int xh  = q_ & 1;
    const int row = q_ >> 1;

    float acc[36];
    #pragma unroll
    for (int i = 0; i < 36; i++) acc[i] = 0.f;

    const int sc_off = row*TW + xh*4;
    const int sh_off = (row + dy)*HPITCH + xh*4;

    for (int k = 0; k < NCHUNK; k++) {
        if (k + 1 < NCHUNK) prefetch(k + 1, (k + 1) & 1);
        if (k + 1 < NCHUNK) asm volatile("cp.async.wait_group 1;\n");
        else                asm volatile("cp.async.wait_group 0;\n");
        __syncthreads();

        const float* bb  = smem + (k & 1) * BUF_FLOATS;
        const float* scp = bb + sc_off;
        const float* shp = bb + CCH*SC_CH + sh_off;
        #pragma unroll 4
        for (int c = 0; c < CCH; c++) {
            float4 v4 = *(const float4*)scp;
            float4 h0 = *(const float4*)shp;
            float4 h1 = *(const float4*)(shp + 4);
            float4 h2 = *(const float4*)(shp + 8);
            scp += SC_CH;
            shp += SH_CH;
            float v[4]  = {v4.x, v4.y, v4.z, v4.w};
            float h[12] = {h0.x, h0.y, h0.z, h0.w,
                           h1.x, h1.y, h1.z, h1.w,
                           h2.x, h2.y, h2.z, h2.w};
            #pragma unroll
            for (int i = 0; i < 4; i++)
                #pragma unroll
                for (int dx = 0; dx < 9; dx++)
                    acc[i*9 + dx] = fmaf(v[i], h[i + dx], acc[i*9 + dx]);
        }
        __syncthreads();
    }

    // ---- dump raw accumulators to rbuf [112][81] (aliases buffers) ----
    {
        float* rb = smem;
        #pragma unroll
        for (int i = 0; i < 4; i++) {
            int pix = row*TW + xh*4 + i;
            #pragma unroll
            for (int dx = 0; dx < 9; dx++)
                rb[pix*81 + dy*9 + dx] = acc[i*9 + dx];
        }
    }
    __syncthreads();

    // ---- postprocess: one thread per pixel ----
    if (t < NPIX) {
        const float* r = smem + t*81;
        int ly = t / TW, lx = t % TW;
        const float* ph = inPh + ly*HPITCH + lx;
        // q[k] = raw[k] * inP(p+delta); argmax (first wins) over q
        float best = -INFINITY;
        int bi = 0;
        #pragma unroll
        for (int ky = 0; ky < 9; ky++)
            #pragma unroll
            for (int kx = 0; kx < 9; kx++) {
                float v = r[ky*9 + kx] * ph[ky*HPITCH + kx];
                if (v > best) { best = v; bi = ky*9 + kx; }
            }
        int biy = bi / 9, bix = bi - biy*9;
        float s = 0.f, sumh = 0.f, sumv = 0.f;
        #pragma unroll
        for (int ky = 0; ky < 9; ky++) {
            float ddy = (float)(ky - biy);
            float dy2 = ddy*ddy;
            #pragma unroll
            for (int kx = 0; kx < 9; kx++) {
                float ddx = (float)(kx - bix);
                float g = expf(-50.0f * (dy2 + ddx*ddx));   // 1/(2*0.1^2)
                // common factor inC cancels in the ratio; BETA kept for s+1e-12
                float f = g * (r[ky*9 + kx] * ph[ky*HPITCH + kx]) * 10.0f;
                s    += f;
                sumh += f * (float)(ky - 4);
                sumv += f * (float)(kx - 4);
            }
        }
        s += 1e-12f;
        int o = (ty0 + ly)*W + tx0 + lx;
        float ic = inC[o];
        outp[o]        = (sumh * ic) / (s * ic);   // == sumh/s, keep exact form cheap
        outp[HW + o]   = (sumv * ic) / (s * ic);
        outp[2*HW + o] = best * ic;                // conf = inC * max(raw*inP)
    }
}

// ---------------------------------------------------------------------------
extern "C" void kernel_launch(void* const* d_in, const int* in_sizes, int n_in,
                              void* d_out, int out_size) {
    const float* x = (const float*)d_in[0];
    float* out = (float*)d_out;

    norm_kernel<<<(B*HW/4 + 255)/256, 256>>>(x);

    const int smem_bytes = SMEM_FLOATS * (int)sizeof(float);   // 72416
    cudaFuncSetAttribute(corr_kernel, cudaFuncAttributeMaxDynamicSharedMemorySize, smem_bytes);

    dim3 grid(W/TW, H/TH, B);   // (7, 4, 64)
    corr_kernel<<<grid, THREADS, smem_bytes>>>(x, out);
}

// round 7
// speedup vs baseline: 3.3843x; 1.4860x over previous
#include <cuda_runtime.h>
#include <math.h>

#define B 64
#define C 256
#define H 56
#define W 56
#define HW (H*W)
#define CHW (C*HW)

#define TW 8            // tile width (centers)
#define TH 14           // tile height (56/14 = 4 exact)
#define HALO_H (TH+8)   // 22
#define HPITCH 20       // padded halo row (floats); cols 0..15 used
#define CCH 16          // channels per smem chunk
#define NCHUNK (C/CCH)  // 16
#define THREADS 126     // 14 rows * 9 dy

#define SC_CH (TH*TW)         // 112 floats per channel (center)
#define SH_CH (HALO_H*HPITCH) // 440 floats per channel (halo)
#define BUF_FLOATS (CCH*(SC_CH+SH_CH))  // 8832
#define NPIX (TH*TW)          // 112
#define INPH_OFF (2*BUF_FLOATS)         // 17664
#define SMEM_FLOATS (INPH_OFF + SH_CH)  // 18104

__device__ float g_inv_norm[B*HW];

__device__ __forceinline__ void cpa16(unsigned dst, const float* src, int srcsz) {
    asm volatile("cp.async.cg.shared.global [%0], [%1], 16, %2;\n"
                 :: "r"(dst), "l"(src), "r"(srcsz));
}
__device__ __forceinline__ void cpa_commit() {
    asm volatile("cp.async.commit_group;\n");
}

// ---------------------------------------------------------------------------
// Pass 1: inv_norm. 4 threads per pixel-quad (64 channels each) + shfl reduce.
// ---------------------------------------------------------------------------
__global__ void norm_kernel(const float* __restrict__ x) {
    int t    = blockIdx.x * blockDim.x + threadIdx.x;
    int unit = t >> 2;          // pixel-quad index, 0..50175
    int cg   = t & 3;           // channel group
    int b    = unit / (HW/4);
    int s4   = unit % (HW/4);
    const float4* px = (const float4*)(x + (size_t)b*CHW + (size_t)cg*64*HW) + s4;
    float a0=0.f, a1=0.f, a2=0.f, a3=0.f;
    #pragma unroll 8
    for (int c = 0; c < 64; c++) {
        float4 v = px[(size_t)c*(HW/4)];
        a0 = fmaf(v.x, v.x, a0);
        a1 = fmaf(v.y, v.y, a1);
        a2 = fmaf(v.z, v.z, a2);
        a3 = fmaf(v.w, v.w, a3);
    }
    a0 += __shfl_xor_sync(0xFFFFFFFFu, a0, 1);
    a1 += __shfl_xor_sync(0xFFFFFFFFu, a1, 1);
    a2 += __shfl_xor_sync(0xFFFFFFFFu, a2, 1);
    a3 += __shfl_xor_sync(0xFFFFFFFFu, a3, 1);
    a0 += __shfl_xor_sync(0xFFFFFFFFu, a0, 2);
    a1 += __shfl_xor_sync(0xFFFFFFFFu, a1, 2);
    a2 += __shfl_xor_sync(0xFFFFFFFFu, a2, 2);
    a3 += __shfl_xor_sync(0xFFFFFFFFu, a3, 2);
    if (cg == 0) {
        float4 r;
        r.x = 1.f / fmaxf(sqrtf(a0), 1e-12f);
        r.y = 1.f / fmaxf(sqrtf(a1), 1e-12f);
        r.z = 1.f / fmaxf(sqrtf(a2), 1e-12f);
        r.w = 1.f / fmaxf(sqrtf(a3), 1e-12f);
        ((float4*)g_inv_norm)[unit] = r;
    }
}

// ---------------------------------------------------------------------------
// Pass 2: raw correlation (norm factored out) + argmax + gaussian soft-argmax
// Grid (7,4,64), 126 threads. Thread: dy = t%9, row = t/9. 8 centers x 9 dx.
// ---------------------------------------------------------------------------
__global__ __launch_bounds__(THREADS, 3)
void corr_kernel(const float* __restrict__ x, float* __restrict__ out) {
    const int tx0 = blockIdx.x * TW;
    const int ty0 = blockIdx.y * TH;
    const int b   = blockIdx.z;

    extern __shared__ float smem[];
    const int t = threadIdx.x;
    float* outp = out + (size_t)b * 3 * HW;

    if ((b & 7) == 0) {   // first frame of each segment: x_post == 0
        for (int i = t; i < NPIX; i += THREADS) {
            int o = (ty0 + i/TW)*W + tx0 + (i%TW);
            outp[o]        = 0.f;
            outp[HW + o]   = 0.f;
            outp[2*HW + o] = 0.f;
        }
        return;
    }

    const float* xc  = x + (size_t)b     * CHW;
    const float* xp  = x + (size_t)(b-1) * CHW;
    const float* inC = g_inv_norm + b     * HW;
    const float* inP = g_inv_norm + (b-1) * HW;

    unsigned smem_u32;
    { unsigned long long tmp;
      asm("cvta.to.shared.u64 %0, %1;" : "=l"(tmp) : "l"(smem));
      smem_u32 = (unsigned)tmp; }

    auto prefetch = [&](int chunk, int buf) {
        const int ch0 = chunk * CCH;
        unsigned bb = smem_u32 + buf * (BUF_FLOATS*4);
        // center: CCH*14*2 = 448 quads
        for (int i = t; i < CCH*TH*2; i += THREADS) {
            int c   = i / (TH*2);
            int rem = i - c*(TH*2);
            int r2  = rem >> 1;
            int lq  = (rem & 1) * 4;
            cpa16(bb + (c*SC_CH + r2*TW + lq)*4,
                  xc + (size_t)(ch0 + c)*HW + (ty0 + r2)*W + tx0 + lq, 16);
        }
        // halo: CCH*22*4 = 1408 quads (quads fully in or out of bounds)
        unsigned hb = bb + CCH*SC_CH*4;
        for (int i = t; i < CCH*HALO_H*4; i += THREADS) {
            int c   = i / (HALO_H*4);
            int rem = i - c*(HALO_H*4);
            int hy  = rem >> 2;
            int hx  = (rem & 3) * 4;
            int gy  = ty0 + hy - 4;
            int gx  = tx0 + hx - 4;
            bool in = (gy >= 0 && gy < H && gx >= 0 && gx < W);
            const float* src = in ? (xp + (size_t)(ch0 + c)*HW + gy*W + gx) : xp;
            cpa16(hb + (c*SH_CH + hy*HPITCH + hx)*4, src, in ? 16 : 0);
        }
        cpa_commit();
    };

    prefetch(0, 0);

    // stage inP halo tile once (postprocess only)
    float* inPh = smem + INPH_OFF;
    for (int i = t; i < SH_CH; i += THREADS) {
        int hy = i / HPITCH, hx = i - hy*HPITCH;
        int gy = ty0 + hy - 4, gx = tx0 + hx - 4;
        inPh[i] = (gy >= 0 && gy < H && gx >= 0 && gx < W && hx < 16)
                  ? inP[gy*W + gx] : 0.f;
    }

    const int dy  = t % 9;
    const int row = t / 9;        // 0..13

    float acc[72];
    #pragma unroll
    for (int i = 0; i < 72; i++) acc[i] = 0.f;

    const int sc_off = row*TW;
    const int sh_off = (row + dy)*HPITCH;

    for (int k = 0; k < NCHUNK; k++) {
        if (k + 1 < NCHUNK) prefetch(k + 1, (k + 1) & 1);
        if (k + 1 < NCHUNK) asm volatile("cp.async.wait_group 1;\n");
        else                asm volatile("cp.async.wait_group 0;\n");
        __syncthreads();

        const float* bb  = smem + (k & 1) * BUF_FLOATS;
        const float* scp = bb + sc_off;
        const float* shp = bb + CCH*SC_CH + sh_off;
        #pragma unroll 2
        for (int c = 0; c < CCH; c++) {
            float4 v0 = *(const float4*)scp;
            float4 v1 = *(const float4*)(scp + 4);
            float4 h0 = *(const float4*)shp;
            float4 h1 = *(const float4*)(shp + 4);
            float4 h2 = *(const float4*)(shp + 8);
            float4 h3 = *(const float4*)(shp + 12);
            scp += SC_CH;
            shp += SH_CH;
            float v[8]  = {v0.x, v0.y, v0.z, v0.w, v1.x, v1.y, v1.z, v1.w};
            float h[16] = {h0.x, h0.y, h0.z, h0.w, h1.x, h1.y, h1.z, h1.w,
                           h2.x, h2.y, h2.z, h2.w, h3.x, h3.y, h3.z, h3.w};
            #pragma unroll
            for (int i = 0; i < 8; i++)
                #pragma unroll
                for (int dx = 0; dx < 9; dx++)
                    acc[i*9 + dx] = fmaf(v[i], h[i + dx], acc[i*9 + dx]);
        }
        __syncthreads();
    }

    // dump raw accumulators to rbuf [112][81] (aliases buffers)
    {
        float* rb = smem;
        #pragma unroll
        for (int i = 0; i < 8; i++) {
            int pix = row*TW + i;
            #pragma unroll
            for (int dx = 0; dx < 9; dx++)
                rb[pix*81 + dy*9 + dx] = acc[i*9 + dx];
        }
    }
    __syncthreads();

    // postprocess: one thread per pixel
    if (t < NPIX) {
        const float* r = smem + t*81;
        int ly = t / TW, lx = t % TW;
        const float* ph = inPh + ly*HPITCH + lx;
        float best = -INFINITY;
        int bi = 0;
        #pragma unroll
        for (int ky = 0; ky < 9; ky++)
            #pragma unroll
            for (int kx = 0; kx < 9; kx++) {
                float v = r[ky*9 + kx] * ph[ky*HPITCH + kx];
                if (v > best) { best = v; bi = ky*9 + kx; }
            }
        int biy = bi / 9, bix = bi - biy*9;
        float s = 0.f, sumh = 0.f, sumv = 0.f;
        #pragma unroll
        for (int ky = 0; ky < 9; ky++) {
            float ddy = (float)(ky - biy);
            float dy2 = ddy*ddy;
            #pragma unroll
            for (int kx = 0; kx < 9; kx++) {
                float ddx = (float)(kx - bix);
                float g = expf(-50.0f * (dy2 + ddx*ddx));   // 1/(2*0.1^2)
                float f = g * (r[ky*9 + kx] * ph[ky*HPITCH + kx]) * 10.0f;
                s    += f;
                sumh += f * (float)(ky - 4);
                sumv += f * (float)(kx - 4);
            }
        }
        s += 1e-12f;
        int o = (ty0 + ly)*W + tx0 + lx;
        float ic = inC[o];
        outp[o]        = sumh / s;
        outp[HW + o]   = sumv / s;
        outp[2*HW + o] = best * ic;   // conf = inC * max(raw*inP)
    }
}

// ---------------------------------------------------------------------------
extern "C" void kernel_launch(void* const* d_in, const int* in_sizes, int n_in,
                              void* d_out, int out_size) {
    const float* x = (const float*)d_in[0];
    float* out = (float*)d_out;

    norm_kernel<<<(B*HW) / 256, 256>>>(x);   // 4 threads per pixel-quad

    const int smem_bytes = SMEM_FLOATS * (int)sizeof(float);   // 72416
    cudaFuncSetAttribute(corr_kernel, cudaFuncAttributeMaxDynamicSharedMemorySize, smem_bytes);

    dim3 grid(W/TW, H/TH, B);   // (7, 4, 64)
    corr_kernel<<<grid, THREADS, smem_bytes>>>(x, out);
}